// round 12
// baseline (speedup 1.0000x reference)
#include <cuda_runtime.h>
#include <cuda_bf16.h>

// FrozenBNBStableEmbedding fused gather+dequant+LayerNorm.
// R12: R5 champion inner loop, UNTOUCHED (REP=16 table, inline scale, v[32],
// LN params from smem, shfl butterfly, __stcs). New shell: persistent grid
// (592 CTAs = 1 wave) + dynamic per-warp token dispatch from a global atomic
// counter (next fetch prefetched to hide ATOMG latency). Counters self-reset
// via a completion atomic so every launch/graph-replay starts at zero.

#define D    1024
#define REP  16
#define EPS  1e-5f
#define GRID 592          // 4 CTAs/SM x 148 SMs -> single wave

__device__ unsigned g_ctr  = 0;   // token dispenser
__device__ unsigned g_done = 0;   // CTA completion count

__global__ __launch_bounds__(256) void emb_ln_kernel(
    const int*   __restrict__ x,
    const int*   __restrict__ w,
    const float* __restrict__ absmax,
    const float* __restrict__ code,
    const float* __restrict__ lnw,
    const float* __restrict__ lnb,
    float*       __restrict__ out,
    int n_tokens)
{
    __shared__ float  s_code[256 * REP];  // s_code[idx*REP + slot]
    __shared__ float4 s_lnw[256];
    __shared__ float4 s_lnb[256];

    const int tid  = threadIdx.x;
    const int lane = tid & 31;

    // Fill replicated code table + LN params (once per CTA)
    {
        const float c = code[tid];
        float4 cv = make_float4(c, c, c, c);
        float4* dst = reinterpret_cast<float4*>(&s_code[tid * REP]);
        dst[0] = cv; dst[1] = cv; dst[2] = cv; dst[3] = cv;
        s_lnw[tid] = __ldg(&reinterpret_cast<const float4*>(lnw)[tid]);
        s_lnb[tid] = __ldg(&reinterpret_cast<const float4*>(lnb)[tid]);
    }
    __syncthreads();

    const float* tab = &s_code[lane & (REP - 1)];

    // Dynamic token dispatch: fetch first token
    unsigned tok;
    if (lane == 0) tok = atomicAdd(&g_ctr, 1u);
    tok = __shfl_sync(0xFFFFFFFFu, tok, 0);

    while (tok < (unsigned)n_tokens) {
        // Prefetch NEXT token id immediately (hides ATOMG ~318cyc latency)
        unsigned tok_next;
        if (lane == 0) tok_next = atomicAdd(&g_ctr, 1u);
        tok_next = __shfl_sync(0xFFFFFFFFu, tok_next, 0);

        // ---- R5 inner loop, verbatim ----
        const int   row   = __ldg(&x[tok]);
        const float scale = __ldg(&absmax[row >> 2]);
        const int4* wrow  = reinterpret_cast<const int4*>(w + (long long)row * D);

        int4 q[8];
        #pragma unroll
        for (int i = 0; i < 8; ++i)
            q[i] = __ldg(&wrow[i * 32 + lane]);

        float v[32];
        float sum = 0.0f, sq = 0.0f;
        #pragma unroll
        for (int i = 0; i < 8; ++i) {
            float a = tab[(q[i].x & 255) * REP] * scale;
            float b = tab[(q[i].y & 255) * REP] * scale;
            float c = tab[(q[i].z & 255) * REP] * scale;
            float d = tab[(q[i].w & 255) * REP] * scale;
            v[i*4+0] = a; v[i*4+1] = b; v[i*4+2] = c; v[i*4+3] = d;
            sum += a + b + c + d;
            sq  += a*a + b*b + c*c + d*d;
        }

        #pragma unroll
        for (int off = 16; off > 0; off >>= 1) {
            sum += __shfl_xor_sync(0xFFFFFFFFu, sum, off);
            sq  += __shfl_xor_sync(0xFFFFFFFFu, sq,  off);
        }
        const float mean = sum * (1.0f / D);
        const float rstd = rsqrtf(sq * (1.0f / D) - mean * mean + EPS);

        float4* orow = reinterpret_cast<float4*>(out) + (long long)tok * (D / 4);
        #pragma unroll
        for (int i = 0; i < 8; ++i) {
            const float4 gw = s_lnw[i * 32 + lane];
            const float4 gb = s_lnb[i * 32 + lane];
            float4 o;
            o.x = (v[i*4+0] - mean) * rstd * gw.x + gb.x;
            o.y = (v[i*4+1] - mean) * rstd * gw.y + gb.y;
            o.z = (v[i*4+2] - mean) * rstd * gw.z + gb.z;
            o.w = (v[i*4+3] - mean) * rstd * gw.w + gb.w;
            __stcs(&orow[i * 32 + lane], o);
        }
        // ---- end R5 inner loop ----

        tok = tok_next;
    }

    // Self-resetting counters: last CTA to finish zeroes both, so the next
    // launch (or graph replay) starts from a clean state.
    __syncthreads();
    if (tid == 0) {
        __threadfence();
        unsigned d = atomicAdd(&g_done, 1u);
        if (d == gridDim.x - 1) {
            g_ctr  = 0;
            g_done = 0;
            __threadfence();
        }
    }
}

extern "C" void kernel_launch(void* const* d_in, const int* in_sizes, int n_in,
                              void* d_out, int out_size)
{
    const int*   x      = (const int*)d_in[0];
    const int*   w      = (const int*)d_in[1];
    const float* absmax = (const float*)d_in[2];
    const float* code   = (const float*)d_in[3];
    const float* lnw    = (const float*)d_in[4];
    const float* lnb    = (const float*)d_in[5];
    float*       out    = (float*)d_out;

    const int n_tokens = in_sizes[0];   // 16384
    emb_ln_kernel<<<GRID, 256>>>(x, w, absmax, code, lnw, lnb, out, n_tokens);
}